// round 1
// baseline (speedup 1.0000x reference)
#include <cuda_runtime.h>

#define NQ 25
#define KVD 9
#define ROW 225          // NQ * KVD
#define WPB 8            // warps (samples) per block
#define THREADS (WPB * 32)

__global__ __launch_bounds__(THREADS)
void attn_fused_kernel(
    const float* __restrict__ x,     const float* __restrict__ mask,
    const float* __restrict__ Wq,    const float* __restrict__ bq,
    const float* __restrict__ Wk,    const float* __restrict__ bk,
    const float* __restrict__ Wv,    const float* __restrict__ bv,
    const float* __restrict__ gamma, const float* __restrict__ beta,
    float* __restrict__ out, int B)
{
    // weights: [proj][group*81], biases: [proj][group*9]
    __shared__ float sW[3][4 * 81];
    __shared__ float sBias[3][4 * 9];
    __shared__ float sMask[NQ];
    __shared__ float sGamma[KVD], sBeta[KVD];
    __shared__ float sK[WPB][ROW];
    __shared__ float sV[WPB][ROW];
    __shared__ float sX[WPB][ROW];   // input staging, reused for output staging

    const int tid  = threadIdx.x;
    const int warp = tid >> 5;
    const int lane = tid & 31;

    // ---- cooperative block-wide load of constants into shared ----
    for (int i = tid; i < 324; i += THREADS) {
        sW[0][i] = Wq[i]; sW[1][i] = Wk[i]; sW[2][i] = Wv[i];
    }
    for (int i = tid; i < 36; i += THREADS) {
        sBias[0][i] = bq[i]; sBias[1][i] = bk[i]; sBias[2][i] = bv[i];
    }
    if (tid < NQ) sMask[tid] = mask[tid] * -1e9f;
    if (tid < KVD) { sGamma[tid] = gamma[tid]; sBeta[tid] = beta[tid]; }

    const long sample = (long)blockIdx.x * WPB + warp;
    const bool valid = (sample < (long)B);

    // ---- per-warp coalesced load of this sample's row into shared ----
    float* sx = sX[warp];
    if (valid) {
        const float* xrow = x + sample * ROW;
        #pragma unroll
        for (int i = lane; i < ROW; i += 32) sx[i] = xrow[i];
    }
    __syncthreads();   // weights + input visible

    float* sk = sK[warp];
    float* sv = sV[warp];

    float xr[KVD];     // residual (this item's input)
    float q[KVD];

    if (valid && lane < NQ) {
        // group of item `lane`: [0,3)->0, [3,13)->1, [13,23)->2, [23,25)->3
        const int g = (lane < 3) ? 0 : (lane < 13) ? 1 : (lane < 23) ? 2 : 3;
        const float* wq = &sW[0][g * 81];
        const float* wk = &sW[1][g * 81];
        const float* wv = &sW[2][g * 81];
        const float* bqg = &sBias[0][g * 9];
        const float* bkg = &sBias[1][g * 9];
        const float* bvg = &sBias[2][g * 9];

        #pragma unroll
        for (int d = 0; d < KVD; d++) xr[d] = sx[lane * KVD + d];

        // projections: out[e] = b[e] + sum_d x[d] * W[e*9+d]   (nn.Linear)
        #pragma unroll
        for (int e = 0; e < KVD; e++) {
            float aq = bqg[e], ak = bkg[e], av = bvg[e];
            #pragma unroll
            for (int d = 0; d < KVD; d++) {
                const float xv = xr[d];
                aq += xv * wq[e * 9 + d];
                ak += xv * wk[e * 9 + d];
                av += xv * wv[e * 9 + d];
            }
            q[e] = aq;
            sk[lane * KVD + e] = ak;   // stride 9 vs 32 banks: conflict-free
            sv[lane * KVD + e] = av;
        }
    }
    __syncwarp();

    if (valid && lane < NQ) {
        // scores + softmax (stable)
        float ev[NQ];
        float mx = -1e30f;
        #pragma unroll
        for (int j = 0; j < NQ; j++) {
            float s = 0.f;
            #pragma unroll
            for (int d = 0; d < KVD; d++) s += q[d] * sk[j * KVD + d];  // broadcast LDS
            s = s * (1.0f / 3.0f) + sMask[j];
            ev[j] = s;
            mx = fmaxf(mx, s);
        }
        float sum = 0.f;
        #pragma unroll
        for (int j = 0; j < NQ; j++) {
            const float e = __expf(ev[j] - mx);
            ev[j] = e;
            sum += e;
        }
        const float inv = 1.0f / sum;

        // out = attn @ V + residual
        float o[KVD];
        #pragma unroll
        for (int d = 0; d < KVD; d++) o[d] = xr[d];
        #pragma unroll
        for (int j = 0; j < NQ; j++) {
            const float w = ev[j] * inv;
            #pragma unroll
            for (int d = 0; d < KVD; d++) o[d] += w * sv[j * KVD + d];
        }

        // layernorm over the 9 dims
        float mu = 0.f;
        #pragma unroll
        for (int d = 0; d < KVD; d++) mu += o[d];
        mu *= (1.0f / 9.0f);
        float var = 0.f;
        #pragma unroll
        for (int d = 0; d < KVD; d++) { const float t = o[d] - mu; var += t * t; }
        var *= (1.0f / 9.0f);
        const float rinv = rsqrtf(var + 1e-5f);
        #pragma unroll
        for (int d = 0; d < KVD; d++)
            sx[lane * KVD + d] = (o[d] - mu) * rinv * sGamma[d] + sBeta[d];
    }
    __syncwarp();

    // ---- per-warp coalesced store ----
    if (valid) {
        float* orow = out + sample * ROW;
        #pragma unroll
        for (int i = lane; i < ROW; i += 32) orow[i] = sx[i];
    }
}

extern "C" void kernel_launch(void* const* d_in, const int* in_sizes, int n_in,
                              void* d_out, int out_size)
{
    const float* x     = (const float*)d_in[0];
    const float* mask  = (const float*)d_in[1];
    const float* Wq    = (const float*)d_in[2];
    const float* bq    = (const float*)d_in[3];
    const float* Wk    = (const float*)d_in[4];
    const float* bk    = (const float*)d_in[5];
    const float* Wv    = (const float*)d_in[6];
    const float* bv    = (const float*)d_in[7];
    const float* gamma = (const float*)d_in[8];
    const float* beta  = (const float*)d_in[9];
    float* out = (float*)d_out;

    const int B = in_sizes[0] / ROW;
    const int blocks = (B + WPB - 1) / WPB;
    attn_fused_kernel<<<blocks, THREADS>>>(x, mask, Wq, bq, Wk, bk, Wv, bv,
                                           gamma, beta, out, B);
}

// round 2
// speedup vs baseline: 1.1583x; 1.1583x over previous
#include <cuda_runtime.h>

#define NQ 25
#define KVD 9
#define ROW 225          // NQ * KVD
#define WPB 8            // warps (samples) per block
#define THREADS (WPB * 32)

typedef unsigned long long u64;

__device__ __forceinline__ u64 pk(float lo, float hi) {
    u64 r; asm("mov.b64 %0,{%1,%2};" : "=l"(r) : "f"(lo), "f"(hi)); return r;
}
__device__ __forceinline__ void unpk(u64 v, float& lo, float& hi) {
    asm("mov.b64 {%0,%1},%2;" : "=f"(lo), "=f"(hi) : "l"(v));
}
__device__ __forceinline__ u64 fma2(u64 a, u64 b, u64 c) {
    u64 d; asm("fma.rn.f32x2 %0,%1,%2,%3;" : "=l"(d) : "l"(a), "l"(b), "l"(c)); return d;
}
__device__ __forceinline__ u64 mul2(u64 a, u64 b) {
    u64 d; asm("mul.rn.f32x2 %0,%1,%2;" : "=l"(d) : "l"(a), "l"(b)); return d;
}

__global__ __launch_bounds__(THREADS)
void attn_fused_kernel(
    const float* __restrict__ x,     const float* __restrict__ mask,
    const float* __restrict__ Wq,    const float* __restrict__ bq,
    const float* __restrict__ Wk,    const float* __restrict__ bk,
    const float* __restrict__ Wv,    const float* __restrict__ bv,
    const float* __restrict__ gamma, const float* __restrict__ beta,
    float* __restrict__ out, int B)
{
    // packed weights: [proj][group][d][pair] (pair = output elems 2p,2p+1; pad to 6)
    __shared__ alignas(16) u64 sWp[3][4][KVD][6];
    __shared__ u64 sBp[3][4][5];
    __shared__ float sMask[NQ];
    __shared__ float sGamma[KVD], sBeta[KVD];
    __shared__ alignas(16) u64 sKp[WPB][NQ][6];
    __shared__ alignas(16) u64 sVp[WPB][NQ][6];
    __shared__ float sX[WPB][ROW];     // in/out staging

    const int tid  = threadIdx.x;
    const int warp = tid >> 5;
    const int lane = tid & 31;

    // ---- repack weights into f32x2 pairs in shared ----
    for (int i = tid; i < 3 * 4 * KVD * 5; i += THREADS) {
        const int p  = i % 5;
        const int d  = (i / 5) % KVD;
        const int g  = (i / 45) % 4;
        const int pr = i / 180;
        const float* W = (pr == 0) ? Wq : (pr == 1) ? Wk : Wv;
        const int e = 2 * p;
        const float l = W[g * 81 + e * KVD + d];
        const float h = (e + 1 < KVD) ? W[g * 81 + (e + 1) * KVD + d] : 0.f;
        sWp[pr][g][d][p] = pk(l, h);
    }
    for (int i = tid; i < 3 * 4 * 5; i += THREADS) {
        const int p  = i % 5;
        const int g  = (i / 5) % 4;
        const int pr = i / 20;
        const float* Bb = (pr == 0) ? bq : (pr == 1) ? bk : bv;
        const int e = 2 * p;
        sBp[pr][g][p] = pk(Bb[g * KVD + e], (e + 1 < KVD) ? Bb[g * KVD + e + 1] : 0.f);
    }
    if (tid < NQ) sMask[tid] = mask[tid] * -1e9f;
    if (tid < KVD) { sGamma[tid] = gamma[tid]; sBeta[tid] = beta[tid]; }

    const long sample = (long)blockIdx.x * WPB + warp;
    const bool valid = (sample < (long)B);

    // ---- coalesced load of this sample's row into shared ----
    float* sx = sX[warp];
    if (valid) {
        const float* xrow = x + sample * ROW;
        #pragma unroll
        for (int i = lane; i < ROW; i += 32) sx[i] = xrow[i];
    }
    __syncthreads();

    u64 qp[5];
    float xr[KVD];

    if (valid && lane < NQ) {
        const int g = (lane < 3) ? 0 : (lane < 13) ? 1 : (lane < 23) ? 2 : 3;

        #pragma unroll
        for (int d = 0; d < KVD; d++) xr[d] = sx[lane * KVD + d];
        u64 xp[KVD];
        #pragma unroll
        for (int d = 0; d < KVD; d++) xp[d] = pk(xr[d], xr[d]);

        u64 acck[5], accv[5];
        #pragma unroll
        for (int p = 0; p < 5; p++) {
            qp[p]   = sBp[0][g][p];
            acck[p] = sBp[1][g][p];
            accv[p] = sBp[2][g][p];
        }

        #pragma unroll
        for (int d = 0; d < KVD; d++) {
            const u64 xd = xp[d];
            {
                const u64* w = &sWp[0][g][d][0];
                const ulonglong2 w01 = *(const ulonglong2*)w;
                const ulonglong2 w23 = *(const ulonglong2*)(w + 2);
                const u64 w4 = w[4];
                qp[0] = fma2(xd, w01.x, qp[0]); qp[1] = fma2(xd, w01.y, qp[1]);
                qp[2] = fma2(xd, w23.x, qp[2]); qp[3] = fma2(xd, w23.y, qp[3]);
                qp[4] = fma2(xd, w4,    qp[4]);
            }
            {
                const u64* w = &sWp[1][g][d][0];
                const ulonglong2 w01 = *(const ulonglong2*)w;
                const ulonglong2 w23 = *(const ulonglong2*)(w + 2);
                const u64 w4 = w[4];
                acck[0] = fma2(xd, w01.x, acck[0]); acck[1] = fma2(xd, w01.y, acck[1]);
                acck[2] = fma2(xd, w23.x, acck[2]); acck[3] = fma2(xd, w23.y, acck[3]);
                acck[4] = fma2(xd, w4,    acck[4]);
            }
            {
                const u64* w = &sWp[2][g][d][0];
                const ulonglong2 w01 = *(const ulonglong2*)w;
                const ulonglong2 w23 = *(const ulonglong2*)(w + 2);
                const u64 w4 = w[4];
                accv[0] = fma2(xd, w01.x, accv[0]); accv[1] = fma2(xd, w01.y, accv[1]);
                accv[2] = fma2(xd, w23.x, accv[2]); accv[3] = fma2(xd, w23.y, accv[3]);
                accv[4] = fma2(xd, w4,    accv[4]);
            }
        }

        u64* krow = &sKp[warp][lane][0];
        u64* vrow = &sVp[warp][lane][0];
        #pragma unroll
        for (int p = 0; p < 5; p++) { krow[p] = acck[p]; vrow[p] = accv[p]; }
    }
    __syncwarp();

    if (valid && lane < NQ) {
        // scores + softmax; pair-4 hi lanes are exact zeros on both sides
        float ev[NQ];
        float mx = -1e30f;
        #pragma unroll
        for (int j = 0; j < NQ; j++) {
            const u64* kr = &sKp[warp][j][0];
            const ulonglong2 k01 = *(const ulonglong2*)kr;
            const ulonglong2 k23 = *(const ulonglong2*)(kr + 2);
            const u64 k4 = kr[4];
            u64 acc = mul2(qp[0], k01.x);
            acc = fma2(qp[1], k01.y, acc);
            acc = fma2(qp[2], k23.x, acc);
            acc = fma2(qp[3], k23.y, acc);
            acc = fma2(qp[4], k4,    acc);
            float a, b; unpk(acc, a, b);
            const float s = (a + b) * (1.0f / 3.0f) + sMask[j];
            ev[j] = s;
            mx = fmaxf(mx, s);
        }
        float sum = 0.f;
        #pragma unroll
        for (int j = 0; j < NQ; j++) {
            const float e = __expf(ev[j] - mx);
            ev[j] = e;
            sum += e;
        }
        const float inv = 1.0f / sum;

        // out = attn @ V + residual (packed accumulators)
        u64 o[5];
        o[0] = pk(xr[0], xr[1]); o[1] = pk(xr[2], xr[3]);
        o[2] = pk(xr[4], xr[5]); o[3] = pk(xr[6], xr[7]);
        o[4] = pk(xr[8], 0.f);
        #pragma unroll
        for (int j = 0; j < NQ; j++) {
            const float w = ev[j] * inv;
            const u64 wp = pk(w, w);
            const u64* vr = &sVp[warp][j][0];
            const ulonglong2 v01 = *(const ulonglong2*)vr;
            const ulonglong2 v23 = *(const ulonglong2*)(vr + 2);
            const u64 v4 = vr[4];
            o[0] = fma2(wp, v01.x, o[0]); o[1] = fma2(wp, v01.y, o[1]);
            o[2] = fma2(wp, v23.x, o[2]); o[3] = fma2(wp, v23.y, o[3]);
            o[4] = fma2(wp, v4,    o[4]);
        }

        float f[KVD + 1];
        unpk(o[0], f[0], f[1]); unpk(o[1], f[2], f[3]);
        unpk(o[2], f[4], f[5]); unpk(o[3], f[6], f[7]);
        unpk(o[4], f[8], f[9]);

        float mu = 0.f;
        #pragma unroll
        for (int d = 0; d < KVD; d++) mu += f[d];
        mu *= (1.0f / 9.0f);
        float var = 0.f;
        #pragma unroll
        for (int d = 0; d < KVD; d++) { const float t = f[d] - mu; var += t * t; }
        var *= (1.0f / 9.0f);
        const float rinv = rsqrtf(var + 1e-5f);
        float* sxo = sX[warp];
        #pragma unroll
        for (int d = 0; d < KVD; d++)
            sxo[lane * KVD + d] = (f[d] - mu) * rinv * sGamma[d] + sBeta[d];
    }
    __syncwarp();

    if (valid) {
        float* orow = out + sample * ROW;
        #pragma unroll
        for (int i = lane; i < ROW; i += 32) orow[i] = sX[warp][i];
    }
}

extern "C" void kernel_launch(void* const* d_in, const int* in_sizes, int n_in,
                              void* d_out, int out_size)
{
    const float* x     = (const float*)d_in[0];
    const float* mask  = (const float*)d_in[1];
    const float* Wq    = (const float*)d_in[2];
    const float* bq    = (const float*)d_in[3];
    const float* Wk    = (const float*)d_in[4];
    const float* bk    = (const float*)d_in[5];
    const float* Wv    = (const float*)d_in[6];
    const float* bv    = (const float*)d_in[7];
    const float* gamma = (const float*)d_in[8];
    const float* beta  = (const float*)d_in[9];
    float* out = (float*)d_out;

    const int B = in_sizes[0] / ROW;
    const int blocks = (B + WPB - 1) / WPB;
    attn_fused_kernel<<<blocks, THREADS>>>(x, mask, Wq, bq, Wk, bk, Wv, bv,
                                           gamma, beta, out, B);
}

// round 3
// speedup vs baseline: 1.1647x; 1.0055x over previous
#include <cuda_runtime.h>

#define NQ 25
#define KVD 9
#define ROW 225
#define WPB 8            // warps per block
#define SPW 2            // samples per warp
#define SPB (WPB*SPW)    // 16 samples per block
#define THREADS (WPB*32)

typedef unsigned long long u64;

__device__ __forceinline__ u64 pk(float lo, float hi) {
    u64 r; asm("mov.b64 %0,{%1,%2};" : "=l"(r) : "f"(lo), "f"(hi)); return r;
}
__device__ __forceinline__ void unpk(u64 v, float& lo, float& hi) {
    asm("mov.b64 {%0,%1},%2;" : "=f"(lo), "=f"(hi) : "l"(v));
}
__device__ __forceinline__ u64 fma2(u64 a, u64 b, u64 c) {
    u64 d; asm("fma.rn.f32x2 %0,%1,%2,%3;" : "=l"(d) : "l"(a), "l"(b), "l"(c)); return d;
}
__device__ __forceinline__ u64 mul2(u64 a, u64 b) {
    u64 d; asm("mul.rn.f32x2 %0,%1,%2;" : "=l"(d) : "l"(a), "l"(b)); return d;
}
__device__ __forceinline__ u64 add2(u64 a, u64 b) {
    u64 d; asm("add.rn.f32x2 %0,%1,%2;" : "=l"(d) : "l"(a), "l"(b)); return d;
}

__global__ __launch_bounds__(THREADS)
void attn_fused_kernel(
    const float* __restrict__ x,     const float* __restrict__ mask,
    const float* __restrict__ Wq,    const float* __restrict__ bq,
    const float* __restrict__ Wk,    const float* __restrict__ bk,
    const float* __restrict__ Wv,    const float* __restrict__ bv,
    const float* __restrict__ gamma, const float* __restrict__ beta,
    float* __restrict__ out, int B)
{
    // packed weights [proj][group][d][pair(5)+pad]; Wq,bq pre-scaled by 1/3
    __shared__ alignas(16) u64 sW[3][4][KVD][6];
    __shared__ alignas(16) u64 sB[3][4][6];
    __shared__ alignas(16) u64 sG[6], sBt[6];
    __shared__ float sMaskF[32];
    // per-(warp,sample) K+V: row j = [k pairs 0..4 | pad | v pairs 0..4 | pad], 96B
    __shared__ alignas(16) u64 sKV[WPB][SPW][NQ][12];

    const int tid  = threadIdx.x;
    const int warp = tid >> 5;
    const int lane = tid & 31;

    // ---- repack constants ----
    for (int i = tid; i < 540; i += THREADS) {
        const int p  = i % 5;
        const int d  = (i / 5) % KVD;
        const int g  = (i / 45) % 4;
        const int pr = i / 180;
        const float* W = (pr == 0) ? Wq : (pr == 1) ? Wk : Wv;
        const float sc = (pr == 0) ? (1.0f / 3.0f) : 1.0f;
        const int e = 2 * p;
        const float lo = W[g * 81 + e * KVD + d] * sc;
        const float hi = (e + 1 < KVD) ? W[g * 81 + (e + 1) * KVD + d] * sc : 0.f;
        sW[pr][g][d][p] = pk(lo, hi);
    }
    for (int i = tid; i < 60; i += THREADS) {
        const int p  = i % 5;
        const int g  = (i / 5) % 4;
        const int pr = i / 20;
        const float* Bb = (pr == 0) ? bq : (pr == 1) ? bk : bv;
        const float sc = (pr == 0) ? (1.0f / 3.0f) : 1.0f;
        const int e = 2 * p;
        const float lo = Bb[g * KVD + e] * sc;
        float hi;
        if (e + 1 < KVD) hi = Bb[g * KVD + e + 1] * sc;
        else             hi = (pr == 0) ? 1.0f : 0.0f;   // q aug slot = 1.0
        sB[pr][g][p] = pk(lo, hi);
    }
    if (tid < 5) {
        const int e = 2 * tid;
        sG[tid]  = pk(gamma[e], (e + 1 < KVD) ? gamma[e + 1] : 0.f);
        sBt[tid] = pk(beta[e],  (e + 1 < KVD) ? beta[e + 1]  : 0.f);
    }
    if (tid < NQ) sMaskF[tid] = mask[tid] * -1e9f;
    __syncthreads();

    const long s0 = (long)blockIdx.x * SPB + warp * SPW;
    const bool v0 = (s0 < (long)B);
    const bool v1 = (s0 + 1 < (long)B);

    u64 qa[5], qb[5];
    float xa[KVD], xb[KVD];
    float suma = 0.f, sumb = 0.f;
    u64 oa[5] = {0,0,0,0,0}, ob[5] = {0,0,0,0,0};

    if (lane < NQ) {
        const int g = (lane < 3) ? 0 : (lane < 13) ? 1 : (lane < 23) ? 2 : 3;

        // direct global read of this item's 9 inputs (residual)
        const float* xr0 = x + s0 * ROW + lane * KVD;
        const float* xr1 = xr0 + ROW;
        #pragma unroll
        for (int d = 0; d < KVD; d++) {
            xa[d] = v0 ? xr0[d] : 0.f;
            xb[d] = v1 ? xr1[d] : 0.f;
        }

        // init accumulators from biases (shared across the 2 samples)
        u64 ka[5], va[5], kb[5], vb[5];
        #pragma unroll
        for (int p = 0; p < 5; p++) {
            const u64 b0 = sB[0][g][p], b1 = sB[1][g][p], b2 = sB[2][g][p];
            qa[p] = b0; qb[p] = b0;
            ka[p] = b1; kb[p] = b1;
            va[p] = b2; vb[p] = b2;
        }

        // projections: weight pairs loaded once, applied to both samples
        #pragma unroll
        for (int d = 0; d < KVD; d++) {
            const u64 x0 = pk(xa[d], xa[d]);
            const u64 x1 = pk(xb[d], xb[d]);
            {
                const u64* w = &sW[0][g][d][0];
                const ulonglong2 w01 = *(const ulonglong2*)w;
                const ulonglong2 w23 = *(const ulonglong2*)(w + 2);
                const u64 w4 = w[4];
                qa[0]=fma2(x0,w01.x,qa[0]); qa[1]=fma2(x0,w01.y,qa[1]);
                qa[2]=fma2(x0,w23.x,qa[2]); qa[3]=fma2(x0,w23.y,qa[3]);
                qa[4]=fma2(x0,w4,   qa[4]);
                qb[0]=fma2(x1,w01.x,qb[0]); qb[1]=fma2(x1,w01.y,qb[1]);
                qb[2]=fma2(x1,w23.x,qb[2]); qb[3]=fma2(x1,w23.y,qb[3]);
                qb[4]=fma2(x1,w4,   qb[4]);
            }
            {
                const u64* w = &sW[1][g][d][0];
                const ulonglong2 w01 = *(const ulonglong2*)w;
                const ulonglong2 w23 = *(const ulonglong2*)(w + 2);
                const u64 w4 = w[4];
                ka[0]=fma2(x0,w01.x,ka[0]); ka[1]=fma2(x0,w01.y,ka[1]);
                ka[2]=fma2(x0,w23.x,ka[2]); ka[3]=fma2(x0,w23.y,ka[3]);
                ka[4]=fma2(x0,w4,   ka[4]);
                kb[0]=fma2(x1,w01.x,kb[0]); kb[1]=fma2(x1,w01.y,kb[1]);
                kb[2]=fma2(x1,w23.x,kb[2]); kb[3]=fma2(x1,w23.y,kb[3]);
                kb[4]=fma2(x1,w4,   kb[4]);
            }
            {
                const u64* w = &sW[2][g][d][0];
                const ulonglong2 w01 = *(const ulonglong2*)w;
                const ulonglong2 w23 = *(const ulonglong2*)(w + 2);
                const u64 w4 = w[4];
                va[0]=fma2(x0,w01.x,va[0]); va[1]=fma2(x0,w01.y,va[1]);
                va[2]=fma2(x0,w23.x,va[2]); va[3]=fma2(x0,w23.y,va[3]);
                va[4]=fma2(x0,w4,   va[4]);
                vb[0]=fma2(x1,w01.x,vb[0]); vb[1]=fma2(x1,w01.y,vb[1]);
                vb[2]=fma2(x1,w23.x,vb[2]); vb[3]=fma2(x1,w23.y,vb[3]);
                vb[4]=fma2(x1,w4,   vb[4]);
            }
        }

        // write K (with mask-augmented slot) and V rows
        const float mterm = sMaskF[lane];  // mask[lane] * -1e9
        float klo, khi;
        u64* ra = &sKV[warp][0][lane][0];
        unpk(ka[4], klo, khi);
        *(ulonglong2*)(ra + 0) = make_ulonglong2(ka[0], ka[1]);
        *(ulonglong2*)(ra + 2) = make_ulonglong2(ka[2], ka[3]);
        ra[4] = pk(klo, mterm);
        *(ulonglong2*)(ra + 6) = make_ulonglong2(va[0], va[1]);
        *(ulonglong2*)(ra + 8) = make_ulonglong2(va[2], va[3]);
        ra[10] = va[4];
        u64* rb = &sKV[warp][1][lane][0];
        unpk(kb[4], klo, khi);
        *(ulonglong2*)(rb + 0) = make_ulonglong2(kb[0], kb[1]);
        *(ulonglong2*)(rb + 2) = make_ulonglong2(kb[2], kb[3]);
        rb[4] = pk(klo, mterm);
        *(ulonglong2*)(rb + 6) = make_ulonglong2(vb[0], vb[1]);
        *(ulonglong2*)(rb + 8) = make_ulonglong2(vb[2], vb[3]);
        rb[10] = vb[4];
    }
    __syncwarp();

    if (lane < NQ) {
        const u64* base0 = &sKV[warp][0][0][0];
        const u64* base1 = &sKV[warp][1][0][0];

        // fused score + exp + attn@V single pass (scale & mask folded into q/k)
        #pragma unroll
        for (int j = 0; j < NQ; j++) {
            {
                const u64* r = base0 + j * 12;
                const ulonglong2 k01 = *(const ulonglong2*)r;
                const ulonglong2 k23 = *(const ulonglong2*)(r + 2);
                const u64 k4 = r[4];
                u64 acc = mul2(qa[0], k01.x);
                acc = fma2(qa[1], k01.y, acc);
                acc = fma2(qa[2], k23.x, acc);
                acc = fma2(qa[3], k23.y, acc);
                acc = fma2(qa[4], k4,    acc);
                float lo, hi; unpk(acc, lo, hi);
                const float e = __expf(lo + hi);
                suma += e;
                const u64 ep = pk(e, e);
                const ulonglong2 v01 = *(const ulonglong2*)(r + 6);
                const ulonglong2 v23 = *(const ulonglong2*)(r + 8);
                const u64 v4 = r[10];
                oa[0]=fma2(ep,v01.x,oa[0]); oa[1]=fma2(ep,v01.y,oa[1]);
                oa[2]=fma2(ep,v23.x,oa[2]); oa[3]=fma2(ep,v23.y,oa[3]);
                oa[4]=fma2(ep,v4,   oa[4]);
            }
            {
                const u64* r = base1 + j * 12;
                const ulonglong2 k01 = *(const ulonglong2*)r;
                const ulonglong2 k23 = *(const ulonglong2*)(r + 2);
                const u64 k4 = r[4];
                u64 acc = mul2(qb[0], k01.x);
                acc = fma2(qb[1], k01.y, acc);
                acc = fma2(qb[2], k23.x, acc);
                acc = fma2(qb[3], k23.y, acc);
                acc = fma2(qb[4], k4,    acc);
                float lo, hi; unpk(acc, lo, hi);
                const float e = __expf(lo + hi);
                sumb += e;
                const u64 ep = pk(e, e);
                const ulonglong2 v01 = *(const ulonglong2*)(r + 6);
                const ulonglong2 v23 = *(const ulonglong2*)(r + 8);
                const u64 v4 = r[10];
                ob[0]=fma2(ep,v01.x,ob[0]); ob[1]=fma2(ep,v01.y,ob[1]);
                ob[2]=fma2(ep,v23.x,ob[2]); ob[3]=fma2(ep,v23.y,ob[3]);
                ob[4]=fma2(ep,v4,   ob[4]);
            }
        }

        // epilogue: normalize, residual, layernorm, direct global store
        const u64 g01 = sG[0],  g1p = sG[1],  g2p = sG[2],  g3p = sG[3];
        const u64 b01 = sBt[0], b1p = sBt[1], b2p = sBt[2], b3p = sBt[3];
        float g8, b8, tmpz;
        unpk(sG[4], g8, tmpz); unpk(sBt[4], b8, tmpz);

        #pragma unroll
        for (int s = 0; s < SPW; s++) {
            const u64* o  = (s == 0) ? oa : ob;
            const float* xr = (s == 0) ? xa : xb;
            const float sum = (s == 0) ? suma : sumb;
            const bool vv = (s == 0) ? v0 : v1;
            if (!vv) continue;

            const float inv = 1.0f / sum;
            const u64 inv2 = pk(inv, inv);
            u64 f[5];
            f[0] = fma2(o[0], inv2, pk(xr[0], xr[1]));
            f[1] = fma2(o[1], inv2, pk(xr[2], xr[3]));
            f[2] = fma2(o[2], inv2, pk(xr[4], xr[5]));
            f[3] = fma2(o[3], inv2, pk(xr[6], xr[7]));
            f[4] = fma2(o[4], inv2, pk(xr[8], 0.f));   // hi stays 0

            float e0,e1,e2,e3,e4,e5,e6,e7,e8,ez;
            unpk(f[0], e0, e1); unpk(f[1], e2, e3);
            unpk(f[2], e4, e5); unpk(f[3], e6, e7);
            unpk(f[4], e8, ez);
            const float mu = (e0+e1+e2+e3+e4+e5+e6+e7+e8) * (1.0f/9.0f);
            const u64 nmu2 = pk(-mu, -mu);
            const u64 t0 = add2(f[0], nmu2);
            const u64 t1 = add2(f[1], nmu2);
            const u64 t2 = add2(f[2], nmu2);
            const u64 t3 = add2(f[3], nmu2);
            const float t8 = e8 - mu;
            u64 vacc = mul2(t0, t0);
            vacc = fma2(t1, t1, vacc);
            vacc = fma2(t2, t2, vacc);
            vacc = fma2(t3, t3, vacc);
            float va0, va1; unpk(vacc, va0, va1);
            const float var = (va0 + va1 + t8 * t8) * (1.0f/9.0f);
            const float rinv = rsqrtf(var + 1e-5f);
            const u64 rinv2 = pk(rinv, rinv);

            const u64 r0 = fma2(mul2(t0, rinv2), g01, b01);
            const u64 r1 = fma2(mul2(t1, rinv2), g1p, b1p);
            const u64 r2 = fma2(mul2(t2, rinv2), g2p, b2p);
            const u64 r3 = fma2(mul2(t3, rinv2), g3p, b3p);
            const float r8 = t8 * rinv * g8 + b8;

            float* orow = out + (s0 + s) * ROW + lane * KVD;
            float w0,w1,w2,w3,w4,w5,w6,w7;
            unpk(r0,w0,w1); unpk(r1,w2,w3); unpk(r2,w4,w5); unpk(r3,w6,w7);
            orow[0]=w0; orow[1]=w1; orow[2]=w2; orow[3]=w3;
            orow[4]=w4; orow[5]=w5; orow[6]=w6; orow[7]=w7; orow[8]=r8;
        }
    }
}

extern "C" void kernel_launch(void* const* d_in, const int* in_sizes, int n_in,
                              void* d_out, int out_size)
{
    const float* x     = (const float*)d_in[0];
    const float* mask  = (const float*)d_in[1];
    const float* Wq    = (const float*)d_in[2];
    const float* bq    = (const float*)d_in[3];
    const float* Wk    = (const float*)d_in[4];
    const float* bk    = (const float*)d_in[5];
    const float* Wv    = (const float*)d_in[6];
    const float* bv    = (const float*)d_in[7];
    const float* gamma = (const float*)d_in[8];
    const float* beta  = (const float*)d_in[9];
    float* out = (float*)d_out;

    const int B = in_sizes[0] / ROW;
    const int blocks = (B + SPB - 1) / SPB;
    attn_fused_kernel<<<blocks, THREADS>>>(x, mask, Wq, bq, Wk, bk, Wv, bv,
                                           gamma, beta, out, B);
}

// round 4
// speedup vs baseline: 1.1948x; 1.0259x over previous
#include <cuda_runtime.h>

#define NQ 25
#define KVD 9
#define ROW 225
#define WPB 8            // warps (samples) per block
#define THREADS (WPB*32)

typedef unsigned long long u64;

__device__ __forceinline__ u64 pk(float lo, float hi) {
    u64 r; asm("mov.b64 %0,{%1,%2};" : "=l"(r) : "f"(lo), "f"(hi)); return r;
}
__device__ __forceinline__ void unpk(u64 v, float& lo, float& hi) {
    asm("mov.b64 {%0,%1},%2;" : "=f"(lo), "=f"(hi) : "l"(v));
}
__device__ __forceinline__ u64 fma2(u64 a, u64 b, u64 c) {
    u64 d; asm("fma.rn.f32x2 %0,%1,%2,%3;" : "=l"(d) : "l"(a), "l"(b), "l"(c)); return d;
}
__device__ __forceinline__ u64 mul2(u64 a, u64 b) {
    u64 d; asm("mul.rn.f32x2 %0,%1,%2;" : "=l"(d) : "l"(a), "l"(b)); return d;
}
__device__ __forceinline__ u64 add2(u64 a, u64 b) {
    u64 d; asm("add.rn.f32x2 %0,%1,%2;" : "=l"(d) : "l"(a), "l"(b)); return d;
}

__global__ __launch_bounds__(THREADS, 3)
void attn_fused_kernel(
    const float* __restrict__ x,     const float* __restrict__ mask,
    const float* __restrict__ Wq,    const float* __restrict__ bq,
    const float* __restrict__ Wk,    const float* __restrict__ bk,
    const float* __restrict__ Wv,    const float* __restrict__ bv,
    const float* __restrict__ gamma, const float* __restrict__ beta,
    float* __restrict__ out, int B)
{
    // packed weights [proj][group][d][pair(5)+pad]; Wq,bq pre-scaled by 1/3
    __shared__ alignas(16) u64 sW[3][4][KVD][6];
    __shared__ alignas(16) u64 sB[3][4][6];
    __shared__ alignas(16) u64 sG[6], sBt[6];
    __shared__ float sMaskF[32];
    // per-warp K|V: row j = [k01 k23 k4+mask pad | v01 v23 v4 pad] = 96B
    __shared__ alignas(16) u64 sKV[WPB][NQ][12];
    __shared__ float sX[WPB][ROW];   // coalesced in/out staging

    const int tid  = threadIdx.x;
    const int warp = tid >> 5;
    const int lane = tid & 31;

    // ---- repack constants ----
    for (int i = tid; i < 540; i += THREADS) {
        const int p  = i % 5;
        const int d  = (i / 5) % KVD;
        const int g  = (i / 45) % 4;
        const int pr = i / 180;
        const float* W = (pr == 0) ? Wq : (pr == 1) ? Wk : Wv;
        const float sc = (pr == 0) ? (1.0f / 3.0f) : 1.0f;
        const int e = 2 * p;
        const float lo = W[g * 81 + e * KVD + d] * sc;
        const float hi = (e + 1 < KVD) ? W[g * 81 + (e + 1) * KVD + d] * sc : 0.f;
        sW[pr][g][d][p] = pk(lo, hi);
    }
    for (int i = tid; i < 60; i += THREADS) {
        const int p  = i % 5;
        const int g  = (i / 5) % 4;
        const int pr = i / 20;
        const float* Bb = (pr == 0) ? bq : (pr == 1) ? bk : bv;
        const float sc = (pr == 0) ? (1.0f / 3.0f) : 1.0f;
        const int e = 2 * p;
        const float lo = Bb[g * KVD + e] * sc;
        float hi;
        if (e + 1 < KVD) hi = Bb[g * KVD + e + 1] * sc;
        else             hi = (pr == 0) ? 1.0f : 0.0f;   // q aug slot = 1.0 (exact)
        sB[pr][g][p] = pk(lo, hi);
    }
    if (tid < 5) {
        const int e = 2 * tid;
        sG[tid]  = pk(gamma[e], (e + 1 < KVD) ? gamma[e + 1] : 0.f);
        sBt[tid] = pk(beta[e],  (e + 1 < KVD) ? beta[e + 1]  : 0.f);
    }
    if (tid < NQ) sMaskF[tid] = mask[tid] * -1e9f;
    __syncthreads();

    const long sample = (long)blockIdx.x * WPB + warp;
    const bool valid = (sample < (long)B);

    // ---- coalesced input staging ----
    float* sx = sX[warp];
    if (valid) {
        const float* xrow = x + sample * ROW;
        #pragma unroll
        for (int i = lane; i < ROW; i += 32) sx[i] = xrow[i];
    }
    __syncwarp();

    float xr[KVD];
    int g = 0;

    // ---- phase 1: K,V projection → shared (k,v regs die here) ----
    if (lane < NQ) {
        g = (lane < 3) ? 0 : (lane < 13) ? 1 : (lane < 23) ? 2 : 3;
        #pragma unroll
        for (int d = 0; d < KVD; d++) xr[d] = sx[lane * KVD + d];

        u64 k[5], v[5];
        #pragma unroll
        for (int p = 0; p < 5; p++) { k[p] = sB[1][g][p]; v[p] = sB[2][g][p]; }

        #pragma unroll
        for (int d = 0; d < KVD; d++) {
            const u64 xd = pk(xr[d], xr[d]);
            {
                const u64* w = &sW[1][g][d][0];
                const ulonglong2 w01 = *(const ulonglong2*)w;
                const ulonglong2 w23 = *(const ulonglong2*)(w + 2);
                const u64 w4 = w[4];
                k[0]=fma2(xd,w01.x,k[0]); k[1]=fma2(xd,w01.y,k[1]);
                k[2]=fma2(xd,w23.x,k[2]); k[3]=fma2(xd,w23.y,k[3]);
                k[4]=fma2(xd,w4,   k[4]);
            }
            {
                const u64* w = &sW[2][g][d][0];
                const ulonglong2 w01 = *(const ulonglong2*)w;
                const ulonglong2 w23 = *(const ulonglong2*)(w + 2);
                const u64 w4 = w[4];
                v[0]=fma2(xd,w01.x,v[0]); v[1]=fma2(xd,w01.y,v[1]);
                v[2]=fma2(xd,w23.x,v[2]); v[3]=fma2(xd,w23.y,v[3]);
                v[4]=fma2(xd,w4,   v[4]);
            }
        }

        float klo, khi;
        unpk(k[4], klo, khi);
        u64* r = &sKV[warp][lane][0];
        *(ulonglong2*)(r + 0) = make_ulonglong2(k[0], k[1]);
        *(ulonglong2*)(r + 2) = make_ulonglong2(k[2], k[3]);
        r[4] = pk(klo, sMaskF[lane]);          // aug slot carries mask*-1e9
        *(ulonglong2*)(r + 6) = make_ulonglong2(v[0], v[1]);
        *(ulonglong2*)(r + 8) = make_ulonglong2(v[2], v[3]);
        r[10] = v[4];
    }
    __syncwarp();

    // ---- phase 2: Q projection, fused score/exp/attn@V, epilogue ----
    if (lane < NQ) {
        u64 q[5];
        #pragma unroll
        for (int p = 0; p < 5; p++) q[p] = sB[0][g][p];
        #pragma unroll
        for (int d = 0; d < KVD; d++) {
            const u64 xd = pk(xr[d], xr[d]);
            const u64* w = &sW[0][g][d][0];
            const ulonglong2 w01 = *(const ulonglong2*)w;
            const ulonglong2 w23 = *(const ulonglong2*)(w + 2);
            const u64 w4 = w[4];
            q[0]=fma2(xd,w01.x,q[0]); q[1]=fma2(xd,w01.y,q[1]);
            q[2]=fma2(xd,w23.x,q[2]); q[3]=fma2(xd,w23.y,q[3]);
            q[4]=fma2(xd,w4,   q[4]);
        }

        float sum = 0.f;
        u64 o[5] = {0,0,0,0,0};
        const u64* base = &sKV[warp][0][0];
        #pragma unroll
        for (int j = 0; j < NQ; j++) {
            const u64* r = base + j * 12;
            const ulonglong2 k01 = *(const ulonglong2*)r;
            const ulonglong2 k23 = *(const ulonglong2*)(r + 2);
            const u64 k4 = r[4];
            u64 acc = mul2(q[0], k01.x);
            acc = fma2(q[1], k01.y, acc);
            acc = fma2(q[2], k23.x, acc);
            acc = fma2(q[3], k23.y, acc);
            acc = fma2(q[4], k4,    acc);
            float lo, hi; unpk(acc, lo, hi);
            const float e = __expf(lo + hi);
            sum += e;
            const u64 ep = pk(e, e);
            const ulonglong2 v01 = *(const ulonglong2*)(r + 6);
            const ulonglong2 v23 = *(const ulonglong2*)(r + 8);
            const u64 v4 = r[10];
            o[0]=fma2(ep,v01.x,o[0]); o[1]=fma2(ep,v01.y,o[1]);
            o[2]=fma2(ep,v23.x,o[2]); o[3]=fma2(ep,v23.y,o[3]);
            o[4]=fma2(ep,v4,   o[4]);
        }

        // normalize + residual + layernorm
        const float inv = 1.0f / sum;
        const u64 inv2 = pk(inv, inv);
        u64 f0 = fma2(o[0], inv2, pk(xr[0], xr[1]));
        u64 f1 = fma2(o[1], inv2, pk(xr[2], xr[3]));
        u64 f2 = fma2(o[2], inv2, pk(xr[4], xr[5]));
        u64 f3 = fma2(o[3], inv2, pk(xr[6], xr[7]));
        u64 f4 = fma2(o[4], inv2, pk(xr[8], 0.f));   // hi stays 0

        float e0,e1,e2,e3,e4,e5,e6,e7,e8,ez;
        unpk(f0, e0, e1); unpk(f1, e2, e3);
        unpk(f2, e4, e5); unpk(f3, e6, e7);
        unpk(f4, e8, ez);
        const float mu = (e0+e1+e2+e3+e4+e5+e6+e7+e8) * (1.0f/9.0f);
        const u64 nmu2 = pk(-mu, -mu);
        const u64 t0 = add2(f0, nmu2);
        const u64 t1 = add2(f1, nmu2);
        const u64 t2 = add2(f2, nmu2);
        const u64 t3 = add2(f3, nmu2);
        const float t8 = e8 - mu;
        u64 vacc = mul2(t0, t0);
        vacc = fma2(t1, t1, vacc);
        vacc = fma2(t2, t2, vacc);
        vacc = fma2(t3, t3, vacc);
        float va0, va1; unpk(vacc, va0, va1);
        const float var = (va0 + va1 + t8 * t8) * (1.0f/9.0f);
        const float rinv = rsqrtf(var + 1e-5f);
        const u64 rinv2 = pk(rinv, rinv);

        const u64 r0 = fma2(mul2(t0, rinv2), sG[0], sBt[0]);
        const u64 r1 = fma2(mul2(t1, rinv2), sG[1], sBt[1]);
        const u64 r2 = fma2(mul2(t2, rinv2), sG[2], sBt[2]);
        const u64 r3 = fma2(mul2(t3, rinv2), sG[3], sBt[3]);
        float g8, b8, zz;
        unpk(sG[4], g8, zz); unpk(sBt[4], b8, zz);
        const float r8 = t8 * rinv * g8 + b8;

        float w0,w1,w2,w3,w4,w5,w6,w7;
        unpk(r0,w0,w1); unpk(r1,w2,w3); unpk(r2,w4,w5); unpk(r3,w6,w7);
        float* so = sx + lane * KVD;
        so[0]=w0; so[1]=w1; so[2]=w2; so[3]=w3;
        so[4]=w4; so[5]=w5; so[6]=w6; so[7]=w7; so[8]=r8;
    }
    __syncwarp();

    // ---- coalesced output ----
    if (valid) {
        float* orow = out + sample * ROW;
        #pragma unroll
        for (int i = lane; i < ROW; i += 32) orow[i] = sx[i];
    }
}

extern "C" void kernel_launch(void* const* d_in, const int* in_sizes, int n_in,
                              void* d_out, int out_size)
{
    const float* x     = (const float*)d_in[0];
    const float* mask  = (const float*)d_in[1];
    const float* Wq    = (const float*)d_in[2];
    const float* bq    = (const float*)d_in[3];
    const float* Wk    = (const float*)d_in[4];
    const float* bk    = (const float*)d_in[5];
    const float* Wv    = (const float*)d_in[6];
    const float* bv    = (const float*)d_in[7];
    const float* gamma = (const float*)d_in[8];
    const float* beta  = (const float*)d_in[9];
    float* out = (float*)d_out;

    const int B = in_sizes[0] / ROW;
    const int blocks = (B + WPB - 1) / WPB;
    attn_fused_kernel<<<blocks, THREADS>>>(x, mask, Wq, bq, Wk, bk, Wv, bv,
                                           gamma, beta, out, B);
}

// round 8
// speedup vs baseline: 1.4703x; 1.2306x over previous
#include <cuda_runtime.h>

#define NQ 25
#define KVD 9
#define ROW 225
#define WPB 4              // warps per block
#define SPW 2              // samples per warp
#define SPB (WPB*SPW)      // 8 samples per block
#define THREADS (WPB*32)   // 128
#define KVSTRIDE 14        // u64 per K|V row (112B, 16B-aligned)
#define KVROWS 26

typedef unsigned long long u64;

__device__ __forceinline__ u64 pk(float lo, float hi) {
    u64 r; asm("mov.b64 %0,{%1,%2};" : "=l"(r) : "f"(lo), "f"(hi)); return r;
}
__device__ __forceinline__ void unpk(u64 v, float& lo, float& hi) {
    asm("mov.b64 {%0,%1},%2;" : "=f"(lo), "=f"(hi) : "l"(v));
}
__device__ __forceinline__ u64 fma2(u64 a, u64 b, u64 c) {
    u64 d; asm("fma.rn.f32x2 %0,%1,%2,%3;" : "=l"(d) : "l"(a), "l"(b), "l"(c)); return d;
}
__device__ __forceinline__ u64 mul2(u64 a, u64 b) {
    u64 d; asm("mul.rn.f32x2 %0,%1,%2;" : "=l"(d) : "l"(a), "l"(b)); return d;
}
__device__ __forceinline__ u64 add2(u64 a, u64 b) {
    u64 d; asm("add.rn.f32x2 %0,%1,%2;" : "=l"(d) : "l"(a), "l"(b)); return d;
}

__global__ __launch_bounds__(THREADS, 5)
void attn_fused_kernel(
    const float* __restrict__ x,     const float* __restrict__ mask,
    const float* __restrict__ Wq,    const float* __restrict__ bq,
    const float* __restrict__ Wk,    const float* __restrict__ bk,
    const float* __restrict__ Wv,    const float* __restrict__ bv,
    const float* __restrict__ gamma, const float* __restrict__ beta,
    float* __restrict__ out, int B)
{
    __shared__ alignas(16) u64 sW[3][4][KVD][6];
    __shared__ alignas(16) u64 sB[3][4][6];
    __shared__ alignas(16) u64 sG[6], sBt[6];
    __shared__ float sMaskF[32];
    __shared__ alignas(16) u64 sKV[WPB][2][KVROWS][KVSTRIDE];
    __shared__ u64 sQ[WPB][2][26][5];
    __shared__ float sX[WPB][2][ROW];

    const int tid  = threadIdx.x;
    const int warp = tid >> 5;
    const int lane = tid & 31;

    // ---- repack constants ----
    for (int i = tid; i < 540; i += THREADS) {
        const int p  = i % 5;
        const int d  = (i / 5) % KVD;
        const int g  = (i / 45) % 4;
        const int pr = i / 180;
        const float* W = (pr == 0) ? Wq : (pr == 1) ? Wk : Wv;
        const float sc = (pr == 0) ? (1.0f / 3.0f) : 1.0f;
        const int e = 2 * p;
        const float lo = W[g * 81 + e * KVD + d] * sc;
        const float hi = (e + 1 < KVD) ? W[g * 81 + (e + 1) * KVD + d] * sc : 0.f;
        sW[pr][g][d][p] = pk(lo, hi);
    }
    for (int i = tid; i < 60; i += THREADS) {
        const int p  = i % 5;
        const int g  = (i / 5) % 4;
        const int pr = i / 20;
        const float* Bb = (pr == 0) ? bq : (pr == 1) ? bk : bv;
        const float sc = (pr == 0) ? (1.0f / 3.0f) : 1.0f;
        const int e = 2 * p;
        const float lo = Bb[g * KVD + e] * sc;
        float hi;
        if (e + 1 < KVD) hi = Bb[g * KVD + e + 1] * sc;
        else             hi = (pr == 0) ? 1.0f : 0.0f;   // q aug slot = 1.0
        sB[pr][g][p] = pk(lo, hi);
    }
    if (tid < 5) {
        const int e = 2 * tid;
        sG[tid]  = pk(gamma[e], (e + 1 < KVD) ? gamma[e + 1] : 0.f);
        sBt[tid] = pk(beta[e],  (e + 1 < KVD) ? beta[e + 1]  : 0.f);
    }
    if (tid < NQ) sMaskF[tid] = mask[tid] * -1e9f;
    __syncthreads();

    const long s0 = (long)blockIdx.x * SPB + warp * SPW;
    const bool vA = (s0 < (long)B);
    const bool vB = (s0 + 1 < (long)B);

    // ---- coalesced input staging ----
    float* sxAll = &sX[warp][0][0];
    if (vB) {
        const float* xrow = x + s0 * ROW;
        #pragma unroll
        for (int i = lane; i < 2 * ROW; i += 32) sxAll[i] = xrow[i];
    } else if (vA) {
        const float* xrow = x + s0 * ROW;
        #pragma unroll
        for (int i = lane; i < ROW; i += 32) sxAll[i] = xrow[i];
    }
    __syncwarp();

    // ---- phase 1: project K,V,Q for item=lane of BOTH samples ----
    if (lane < NQ) {
        const int g = (lane < 3) ? 0 : (lane < 13) ? 1 : (lane < 23) ? 2 : 3;
        float xa[KVD], xb[KVD];
        #pragma unroll
        for (int d = 0; d < KVD; d++) {
            xa[d] = sX[warp][0][lane * KVD + d];
            xb[d] = sX[warp][1][lane * KVD + d];
        }
        const float mterm = sMaskF[lane];
        u64* ra = &sKV[warp][0][lane][0];
        u64* rb = &sKV[warp][1][lane][0];

        // --- K ---
        {
            u64 kA[5], kB[5];
            #pragma unroll
            for (int p = 0; p < 5; p++) { kA[p] = sB[1][g][p]; kB[p] = kA[p]; }
            #pragma unroll
            for (int d = 0; d < KVD; d++) {
                const u64 x0 = pk(xa[d], xa[d]);
                const u64 x1 = pk(xb[d], xb[d]);
                const u64* w = &sW[1][g][d][0];
                const ulonglong2 w01 = *(const ulonglong2*)w;
                const ulonglong2 w23 = *(const ulonglong2*)(w + 2);
                const u64 w4 = w[4];
                kA[0]=fma2(x0,w01.x,kA[0]); kA[1]=fma2(x0,w01.y,kA[1]);
                kA[2]=fma2(x0,w23.x,kA[2]); kA[3]=fma2(x0,w23.y,kA[3]);
                kA[4]=fma2(x0,w4,   kA[4]);
                kB[0]=fma2(x1,w01.x,kB[0]); kB[1]=fma2(x1,w01.y,kB[1]);
                kB[2]=fma2(x1,w23.x,kB[2]); kB[3]=fma2(x1,w23.y,kB[3]);
                kB[4]=fma2(x1,w4,   kB[4]);
            }
            float klo, khi;
            unpk(kA[4], klo, khi);
            *(ulonglong2*)(ra + 0) = make_ulonglong2(kA[0], kA[1]);
            *(ulonglong2*)(ra + 2) = make_ulonglong2(kA[2], kA[3]);
            ra[4] = pk(klo, mterm);
            unpk(kB[4], klo, khi);
            *(ulonglong2*)(rb + 0) = make_ulonglong2(kB[0], kB[1]);
            *(ulonglong2*)(rb + 2) = make_ulonglong2(kB[2], kB[3]);
            rb[4] = pk(klo, mterm);
        }
        // --- V ---
        {
            u64 vAr[5], vBr[5];
            #pragma unroll
            for (int p = 0; p < 5; p++) { vAr[p] = sB[2][g][p]; vBr[p] = vAr[p]; }
            #pragma unroll
            for (int d = 0; d < KVD; d++) {
                const u64 x0 = pk(xa[d], xa[d]);
                const u64 x1 = pk(xb[d], xb[d]);
                const u64* w = &sW[2][g][d][0];
                const ulonglong2 w01 = *(const ulonglong2*)w;
                const ulonglong2 w23 = *(const ulonglong2*)(w + 2);
                const u64 w4 = w[4];
                vAr[0]=fma2(x0,w01.x,vAr[0]); vAr[1]=fma2(x0,w01.y,vAr[1]);
                vAr[2]=fma2(x0,w23.x,vAr[2]); vAr[3]=fma2(x0,w23.y,vAr[3]);
                vAr[4]=fma2(x0,w4,   vAr[4]);
                vBr[0]=fma2(x1,w01.x,vBr[0]); vBr[1]=fma2(x1,w01.y,vBr[1]);
                vBr[2]=fma2(x1,w23.x,vBr[2]); vBr[3]=fma2(x1,w23.y,vBr[3]);
                vBr[4]=fma2(x1,w4,   vBr[4]);
            }
            *(ulonglong2*)(ra + 6) = make_ulonglong2(vAr[0], vAr[1]);
            *(ulonglong2*)(ra + 8) = make_ulonglong2(vAr[2], vAr[3]);
            ra[10] = vAr[4];
            *(ulonglong2*)(rb + 6) = make_ulonglong2(vBr[0], vBr[1]);
            *(ulonglong2*)(rb + 8) = make_ulonglong2(vBr[2], vBr[3]);
            rb[10] = vBr[4];
        }
        // --- Q ---
        {
            u64 qA[5], qB[5];
            #pragma unroll
            for (int p = 0; p < 5; p++) { qA[p] = sB[0][g][p]; qB[p] = qA[p]; }
            #pragma unroll
            for (int d = 0; d < KVD; d++) {
                const u64 x0 = pk(xa[d], xa[d]);
                const u64 x1 = pk(xb[d], xb[d]);
                const u64* w = &sW[0][g][d][0];
                const ulonglong2 w01 = *(const ulonglong2*)w;
                const ulonglong2 w23 = *(const ulonglong2*)(w + 2);
                const u64 w4 = w[4];
                qA[0]=fma2(x0,w01.x,qA[0]); qA[1]=fma2(x0,w01.y,qA[1]);
                qA[2]=fma2(x0,w23.x,qA[2]); qA[3]=fma2(x0,w23.y,qA[3]);
                qA[4]=fma2(x0,w4,   qA[4]);
                qB[0]=fma2(x1,w01.x,qB[0]); qB[1]=fma2(x1,w01.y,qB[1]);
                qB[2]=fma2(x1,w23.x,qB[2]); qB[3]=fma2(x1,w23.y,qB[3]);
                qB[4]=fma2(x1,w4,   qB[4]);
            }
            #pragma unroll
            for (int p = 0; p < 5; p++) {
                sQ[warp][0][lane][p] = qA[p];
                sQ[warp][1][lane][p] = qB[p];
            }
        }
    }
    __syncwarp();

    // ---- phase 2: lanes 0-12 -> sample A, 13-25 -> sample B; 2 q-rows/lane ----
    if (lane < 26) {
        const int sel  = (lane >= 13) ? 1 : 0;
        const int h    = lane - 13 * sel;
        const int r0   = 2 * h;
        const bool has1 = (2 * h + 1 < NQ);         // lane h=12: row 25 doesn't exist
        const int r1   = has1 ? (2 * h + 1) : (NQ - 1);

        u64 q[2][5];
        #pragma unroll
        for (int p = 0; p < 5; p++) {
            q[0][p] = sQ[warp][sel][r0][p];
            q[1][p] = sQ[warp][sel][r1][p];
        }

        u64 o[2][5];
        float sum[2] = {0.f, 0.f};
        #pragma unroll
        for (int p = 0; p < 5; p++) { o[0][p] = 0; o[1][p] = 0; }

        const u64* base = &sKV[warp][sel][0][0];
        #pragma unroll
        for (int j = 0; j < NQ; j++) {
            const u64* r = base + j * KVSTRIDE;
            const ulonglong2 k01 = *(const ulonglong2*)r;
            const ulonglong2 k23 = *(const ulonglong2*)(r + 2);
            const u64 k4 = r[4];
            u64 ep[2];
            #pragma unroll
            for (int s = 0; s < 2; s++) {
                u64 acc = mul2(q[s][0], k01.x);
                acc = fma2(q[s][1], k01.y, acc);
                acc = fma2(q[s][2], k23.x, acc);
                acc = fma2(q[s][3], k23.y, acc);
                acc = fma2(q[s][4], k4,    acc);
                float lo, hi; unpk(acc, lo, hi);
                const float e = __expf(lo + hi);
                sum[s] += e;
                ep[s] = pk(e, e);
            }
            const ulonglong2 v01 = *(const ulonglong2*)(r + 6);
            const ulonglong2 v23 = *(const ulonglong2*)(r + 8);
            const u64 v4 = r[10];
            #pragma unroll
            for (int s = 0; s < 2; s++) {
                o[s][0] = fma2(ep[s], v01.x, o[s][0]);
                o[s][1] = fma2(ep[s], v01.y, o[s][1]);
                o[s][2] = fma2(ep[s], v23.x, o[s][2]);
                o[s][3] = fma2(ep[s], v23.y, o[s][3]);
                o[s][4] = fma2(ep[s], v4,    o[s][4]);
            }
        }

        // ---- epilogue per q-row ----
        float g8, b8, zz;
        unpk(sG[4], g8, zz); unpk(sBt[4], b8, zz);
        #pragma unroll
        for (int s = 0; s < 2; s++) {
            if (s == 1 && !has1) break;   // clamped duplicate: row 24 already done by s=0 owner
            const int row = (s == 0) ? r0 : r1;
            float xr[KVD];
            #pragma unroll
            for (int d = 0; d < KVD; d++) xr[d] = sX[warp][sel][row * KVD + d];

            const float inv = 1.0f / sum[s];
            const u64 inv2 = pk(inv, inv);
            const u64 f0 = fma2(o[s][0], inv2, pk(xr[0], xr[1]));
            const u64 f1 = fma2(o[s][1], inv2, pk(xr[2], xr[3]));
            const u64 f2 = fma2(o[s][2], inv2, pk(xr[4], xr[5]));
            const u64 f3 = fma2(o[s][3], inv2, pk(xr[6], xr[7]));
            const u64 f4 = fma2(o[s][4], inv2, pk(xr[8], 0.f));

            float e0,e1,e2,e3,e4,e5,e6,e7,e8,ez;
            unpk(f0, e0, e1); unpk(f1, e2, e3);
            unpk(f2, e4, e5); unpk(f3, e6, e7);
            unpk(f4, e8, ez);
            const float mu = (e0+e1+e2+e3+e4+e5+e6+e7+e8) * (1.0f/9.0f);
            const u64 nmu2 = pk(-mu, -mu);
            const u64 t0 = add2(f0, nmu2);
            const u64 t1 = add2(f1, nmu2);
            const u64 t2 = add2(f2, nmu2);
            const u64 t3 = add2(f3, nmu2);
            const float t8 = e8 - mu;
            u64 vacc = mul2(t0, t0);
            vacc = fma2(t1, t1, vacc);
            vacc = fma2(t2, t2, vacc);
            vacc = fma2(t3, t3, vacc);
            float va0, va1; unpk(vacc, va0, va1);
            const float var = (va0 + va1 + t8 * t8) * (1.0f/9.0f);
            const float rinv = rsqrtf(var + 1e-5f);
            const u64 rinv2 = pk(rinv, rinv);

            const u64 r0p = fma2(mul2(t0, rinv2), sG[0], sBt[0]);
            const u64 r1p = fma2(mul2(t1, rinv2), sG[1], sBt[1]);
            const u64 r2p = fma2(mul2(t2, rinv2), sG[2], sBt[2]);
            const u64 r3p = fma2(mul2(t3, rinv2), sG[3], sBt[3]);
            const float r8 = t8 * rinv * g8 + b8;

            float w0,w1,w2,w3,w4,w5,w6,w7;
            unpk(r0p,w0,w1); unpk(r1p,w2,w3); unpk(r2p,w4,w5); unpk(r3p,w6,w7);
            float* so = &sX[warp][sel][row * KVD];
            so[0]=w0; so[1]=w1; so[2]=w2; so[3]=w3;
            so[4]=w4; so[5]=w5; so[6]=w6; so[7]=w7; so[8]=r8;
        }
    }
    __syncwarp();

    // ---- coalesced output ----
    if (vB) {
        float* orow = out + s0 * ROW;
        #pragma unroll
        for (int i = lane; i < 2 * ROW; i += 32) orow[i] = sxAll[i];
    } else if (vA) {
        float* orow = out + s0 * ROW;
        #pragma unroll
        for (int i = lane; i < ROW; i += 32) orow[i] = sxAll[i];
    }
}

extern "C" void kernel_launch(void* const* d_in, const int* in_sizes, int n_in,
                              void* d_out, int out_size)
{
    const float* x     = (const float*)d_in[0];
    const float* mask  = (const float*)d_in[1];
    const float* Wq    = (const float*)d_in[2];
    const float* bq    = (const float*)d_in[3];
    const float* Wk    = (const float*)d_in[4];
    const float* bk    = (const float*)d_in[5];
    const float* Wv    = (const float*)d_in[6];
    const float* bv    = (const float*)d_in[7];
    const float* gamma = (const float*)d_in[8];
    const float* beta  = (const float*)d_in[9];
    float* out = (float*)d_out;

    const int B = in_sizes[0] / ROW;
    const int blocks = (B + SPB - 1) / SPB;
    attn_fused_kernel<<<blocks, THREADS>>>(x, mask, Wq, bq, Wk, bk, Wv, bv,
                                           gamma, beta, out, B);
}